// round 1
// baseline (speedup 1.0000x reference)
#include <cuda_runtime.h>
#include <cuda_bf16.h>

#define BATCH 8
#define NT    1024
typedef unsigned long long ull;
typedef unsigned int u32;

// ---------------- scratch (__device__ globals; no allocation allowed) ------
__device__ __align__(16) float g_bufA[BATCH * NT * 256];
__device__ __align__(16) float g_bufB[BATCH * NT * 256];
__device__ __align__(16) float g_s  [BATCH * NT * 4];
__device__ __align__(16) float g_Es [BATCH * NT * 4];
__device__ __align__(16) float g_Es2[BATCH * NT * 4];
__device__ __align__(16) float g_d  [BATCH * NT * 4];
__device__ __align__(16) float g_Ed [BATCH * NT * 4];
__device__ __align__(16) float g_Ed2[BATCH * NT * 4];
__device__ __align__(16) u32   g_bits[BATCH * NT * (NT / 32)];
__device__ __align__(16) float g_gsum[BATCH * 64];
__device__ __align__(16) float g_z2[BATCH];

// ---------------- helpers --------------------------------------------------
__device__ __forceinline__ void fma2(ull& d, ull a, ull b) {
    asm("fma.rn.f32x2 %0, %1, %2, %0;" : "+l"(d) : "l"(a), "l"(b));
}
__device__ __forceinline__ ull pack2(float x) {
    unsigned u = __float_as_uint(x);
    ull r;
    asm("mov.b64 %0, {%1, %1};" : "=l"(r) : "r"(u));
    return r;
}

// ---------------- adj bit packing (with self loops) ------------------------
__global__ void pack_adj_kernel(const int* __restrict__ adj, u32* __restrict__ bits) {
    int row = blockIdx.x;                 // b*NT + i
    int lane = threadIdx.x;               // 32 threads
    int i = row & (NT - 1);
    const int* arow = adj + (size_t)row * NT;
    for (int w = 0; w < 32; w++) {
        int j = w * 32 + lane;
        int v = arow[j];
        unsigned m = __ballot_sync(0xffffffffu, (v > 0) || (j == i));
        if (lane == 0) bits[row * 32 + w] = m;
    }
}

// ---------------- feature GEMM: Y[M,Nc] = X[M,K] @ W[Nc,K]^T ---------------
// BM=128, BN=64, TK=16, 256 threads, 8x4 register tile.
__global__ __launch_bounds__(256) void gemm_xwT(
    const float* __restrict__ X, const float* __restrict__ W,
    float* __restrict__ Y, int M, int K, int Nc)
{
    __shared__ float Xs[128][16];
    __shared__ float Ws[64][17];
    int tid = threadIdx.x;
    int m0 = blockIdx.x * 128, n0 = blockIdx.y * 64;
    int tx = tid & 15;          // col group -> cols tx*4..+3
    int ty = tid >> 4;          // row group -> rows ty*8..+7
    float acc[8][4];
#pragma unroll
    for (int r = 0; r < 8; r++)
#pragma unroll
        for (int c = 0; c < 4; c++) acc[r][c] = 0.f;

    for (int k0 = 0; k0 < K; k0 += 16) {
#pragma unroll
        for (int l = 0; l < 2; l++) {
            int f = tid + l * 256;              // 0..511 float4 slots
            int row = f >> 2;
            int kc = (f & 3) * 4;
            float4 v = *(const float4*)&X[(size_t)(m0 + row) * K + k0 + kc];
            Xs[row][kc] = v.x; Xs[row][kc + 1] = v.y;
            Xs[row][kc + 2] = v.z; Xs[row][kc + 3] = v.w;
        }
        {
            int row = tid >> 2;
            int kc = (tid & 3) * 4;
            float4 v = *(const float4*)&W[(size_t)(n0 + row) * K + k0 + kc];
            Ws[row][kc] = v.x; Ws[row][kc + 1] = v.y;
            Ws[row][kc + 2] = v.z; Ws[row][kc + 3] = v.w;
        }
        __syncthreads();
#pragma unroll
        for (int kk = 0; kk < 16; kk++) {
            float a[8], bb[4];
#pragma unroll
            for (int r = 0; r < 8; r++) a[r] = Xs[ty * 8 + r][kk];
#pragma unroll
            for (int c = 0; c < 4; c++) bb[c] = Ws[tx * 4 + c][kk];
#pragma unroll
            for (int r = 0; r < 8; r++)
#pragma unroll
                for (int c = 0; c < 4; c++) acc[r][c] += a[r] * bb[c];
        }
        __syncthreads();
    }
#pragma unroll
    for (int r = 0; r < 8; r++)
#pragma unroll
        for (int c = 0; c < 4; c++)
            Y[(size_t)(m0 + ty * 8 + r) * Nc + n0 + tx * 4 + c] = acc[r][c];
}

// ---------------- attention score precompute -------------------------------
__global__ void scores_kernel(
    const float* __restrict__ feat,
    const float* __restrict__ a_src, const float* __restrict__ a_dst,
    float* __restrict__ s_arr, float* __restrict__ Es_arr, float* __restrict__ Es2_arr,
    float* __restrict__ d_arr, float* __restrict__ Ed_arr, float* __restrict__ Ed2_arr,
    int H)
{
    int gtid = blockIdx.x * blockDim.x + threadIdx.x;
    int wid = gtid >> 5;
    int lane = threadIdx.x & 31;
    if (wid >= BATCH * NT) return;
    const float* frow = feat + (size_t)wid * H * 64;
    for (int h = 0; h < H; h++) {
        float f0 = frow[h * 64 + lane];
        float f1 = frow[h * 64 + 32 + lane];
        float s = f0 * a_src[h * 64 + lane] + f1 * a_src[h * 64 + 32 + lane];
        float d = f0 * a_dst[h * 64 + lane] + f1 * a_dst[h * 64 + 32 + lane];
#pragma unroll
        for (int o = 16; o > 0; o >>= 1) {
            s += __shfl_xor_sync(0xffffffffu, s, o);
            d += __shfl_xor_sync(0xffffffffu, d, o);
        }
        if (lane == 0) {
            int idx = wid * H + h;
            s_arr[idx]   = s;
            Es_arr[idx]  = __expf(s);
            Es2_arr[idx] = __expf(0.2f * s);
            d_arr[idx]   = d;
            Ed_arr[idx]  = __expf(d);
            Ed2_arr[idx] = __expf(0.2f * d);
        }
    }
}

// ---------------- fused masked-softmax aggregation -------------------------
// grid: (NT/64, H, BATCH). Block 256 threads.
// out[b,i,h*64+c] = relu( (sum_j e_ij * feat[b,j,h,c]) / (sum_j e_ij) + bias )
// e_ij = adjbit * ( s_j+d_i>0 ? Es_j*Ed_i : Es2_j*Ed2_i )
__global__ __launch_bounds__(256) void agg_kernel(
    const float* __restrict__ feat,
    const float* __restrict__ s_arr, const float* __restrict__ Es_arr,
    const float* __restrict__ Es2_arr,
    const float* __restrict__ d_arr, const float* __restrict__ Ed_arr,
    const float* __restrict__ Ed2_arr,
    const u32* __restrict__ adjbits,
    const float* __restrict__ bias, float* __restrict__ xout, int H)
{
    __shared__ float  E1[64][65];
    __shared__ float2 hs2[64][33];
    __shared__ float  sj[64], Esj[64], Es2j[64], rowsumsh[64];

    int tid = threadIdx.x;
    int it = blockIdx.x, h = blockIdx.y, b = blockIdx.z;
    int i0 = it * 64;
    int fs = H * 64;

    // E-stage mapping: thread -> (ie, q); handles row i0+ie, j-range q*16..+15
    int ie = tid >> 2, q = tid & 3;
    int irow = b * NT + i0 + ie;
    float d_i   = d_arr[irow * H + h];
    float Ed_i  = Ed_arr[irow * H + h];
    float Ed2_i = Ed2_arr[irow * H + h];
    const u32* adjrow = adjbits + (size_t)irow * 32;
    float rowsum = 0.f;

    // GEMM mapping: thread -> (ti2, tc); rows 2*ti2,2*ti2+1; col-pairs tc+8q
    int tc = tid & 7, ti2 = tid >> 3;
    int r0 = 2 * ti2;
    ull acc[8];
#pragma unroll
    for (int r = 0; r < 8; r++) acc[r] = 0ull;

    const float* fbase = feat + (size_t)b * NT * fs + h * 64;

    for (int j0 = 0; j0 < NT; j0 += 64) {
        __syncthreads();   // previous tile's GEMM reads done before overwrite
        // ---- load h-feature tile (64 x 64 floats) + score meta ----
#pragma unroll
        for (int l = 0; l < 4; l++) {
            int f = tid + l * 256;          // 1024 float4 slots
            int jj = f >> 4;
            int kq = f & 15;
            float4 v = *(const float4*)(fbase + (size_t)(j0 + jj) * fs + kq * 4);
            hs2[jj][kq * 2]     = make_float2(v.x, v.y);
            hs2[jj][kq * 2 + 1] = make_float2(v.z, v.w);
        }
        if (tid < 64)        sj[tid]        = s_arr [(b * NT + j0 + tid) * H + h];
        else if (tid < 128)  Esj[tid - 64]  = Es_arr[(b * NT + j0 + tid - 64) * H + h];
        else if (tid < 192)  Es2j[tid - 128] = Es2_arr[(b * NT + j0 + tid - 128) * H + h];
        __syncthreads();

        // ---- E stage: build masked-exp tile + partial row sums ----
        u32 word = adjrow[(j0 >> 5) + (q >> 1)];
        int sh = (q & 1) * 16;
#pragma unroll
        for (int k = 0; k < 16; k++) {
            int jj = q * 16 + k;
            float p = sj[jj] + d_i;
            float e = (p > 0.f) ? Esj[jj] * Ed_i : Es2j[jj] * Ed2_i;
            e = ((word >> (sh + k)) & 1u) ? e : 0.f;
            rowsum += e;
            E1[ie][jj] = e;
        }
        __syncthreads();

        // ---- rank-64 update with packed f32x2 FMA ----
#pragma unroll 4
        for (int jj = 0; jj < 64; jj++) {
            ull e0 = pack2(E1[r0][jj]);
            ull e1 = pack2(E1[r0 + 1][jj]);
            ull h0 = *(ull*)&hs2[jj][tc];
            ull h1 = *(ull*)&hs2[jj][tc + 8];
            ull h2 = *(ull*)&hs2[jj][tc + 16];
            ull h3 = *(ull*)&hs2[jj][tc + 24];
            fma2(acc[0], e0, h0); fma2(acc[1], e0, h1);
            fma2(acc[2], e0, h2); fma2(acc[3], e0, h3);
            fma2(acc[4], e1, h0); fma2(acc[5], e1, h1);
            fma2(acc[6], e1, h2); fma2(acc[7], e1, h3);
        }
    }

    // ---- reduce rowsum across the 4 q-threads of each row ----
    rowsum += __shfl_xor_sync(0xffffffffu, rowsum, 1);
    rowsum += __shfl_xor_sync(0xffffffffu, rowsum, 2);
    if (q == 0) rowsumsh[ie] = rowsum;
    __syncthreads();

    // ---- epilogue: normalize + bias + relu ----
#pragma unroll
    for (int r = 0; r < 2; r++) {
        int i = r0 + r;
        float rinv = 1.0f / rowsumsh[i];
        float* orow = xout + (size_t)(b * NT + i0 + i) * fs + h * 64;
#pragma unroll
        for (int qq = 0; qq < 4; qq++) {
            int cc = tc + 8 * qq;
            float2 v = *(float2*)&acc[r * 4 + qq];
            float c0 = v.x * rinv + bias[h * 64 + 2 * cc];
            float c1 = v.y * rinv + bias[h * 64 + 2 * cc + 1];
            float2 o = make_float2(fmaxf(c0, 0.f), fmaxf(c1, 0.f));
            *(float2*)&orow[2 * cc] = o;
        }
    }
}

// ---------------- readout --------------------------------------------------
__global__ void gsum_kernel(const float* __restrict__ x, float* __restrict__ g) {
    int b = blockIdx.x;
    int tid = threadIdx.x;         // 256
    int c = tid & 63, nq = tid >> 6;
    float acc = 0.f;
    for (int n = nq; n < NT; n += 4) acc += x[((size_t)b * NT + n) * 64 + c];
    __shared__ float sm[256];
    sm[tid] = acc;
    __syncthreads();
    if (tid < 64) g[b * 64 + tid] = sm[tid] + sm[64 + tid] + sm[128 + tid] + sm[192 + tid];
}

__global__ void z2_kernel(const float* __restrict__ g, const float* __restrict__ wg,
                          const float* __restrict__ bg, const float* __restrict__ wv,
                          float* __restrict__ z2) {
    int b = blockIdx.x;
    int c = threadIdx.x;           // 64
    float acc = bg[c];
    for (int k = 0; k < 64; k++) acc += g[b * 64 + k] * wg[c * 64 + k];
    float y = fmaxf(acc, 0.f) * wv[64 + c];
    __shared__ float sm[64];
    sm[c] = y;
    __syncthreads();
    if (c == 0) {
        float t = 0.f;
        for (int k = 0; k < 64; k++) t += sm[k];
        z2[b] = t;
    }
}

__global__ __launch_bounds__(256) void final_kernel(
    const float* __restrict__ x,
    const float* __restrict__ wn, const float* __restrict__ bn,
    const float* __restrict__ wv, const float* __restrict__ bv,
    const float* __restrict__ z2, float* __restrict__ out)
{
    __shared__ float wns[64][65];
    __shared__ float bns[64], wvs[64];
    int tid = threadIdx.x;
#pragma unroll
    for (int l = 0; l < 16; l++) {
        int f = tid + l * 256;
        wns[f >> 6][f & 63] = wn[f];
    }
    if (tid < 64) { bns[tid] = bn[tid]; wvs[tid] = wv[tid]; }
    __syncthreads();

    int row = blockIdx.x * 64 + (tid >> 2);
    int q = tid & 3;
    float xr[64];
#pragma unroll
    for (int k = 0; k < 64; k++) xr[k] = x[(size_t)row * 64 + k];
    float y = 0.f;
    for (int c16 = 0; c16 < 16; c16++) {
        int c = q * 16 + c16;
        float acc = bns[c];
#pragma unroll
        for (int k = 0; k < 64; k++) acc += xr[k] * wns[c][k];
        y += fmaxf(acc, 0.f) * wvs[c];
    }
    y += __shfl_xor_sync(0xffffffffu, y, 1);
    y += __shfl_xor_sync(0xffffffffu, y, 2);
    if (q == 0) out[row] = y + z2[row >> 10] + bv[0];
}

// ---------------- launch ----------------------------------------------------
extern "C" void kernel_launch(void* const* d_in, const int* in_sizes, int n_in,
                              void* d_out, int out_size)
{
    const float* xin = (const float*)d_in[0];
    const int*   adj = (const int*)d_in[1];
    const float* w1  = (const float*)d_in[2];
    const float* as1 = (const float*)d_in[3];
    const float* ad1 = (const float*)d_in[4];
    const float* b1  = (const float*)d_in[5];
    const float* w2  = (const float*)d_in[6];
    const float* as2 = (const float*)d_in[7];
    const float* ad2 = (const float*)d_in[8];
    const float* b2  = (const float*)d_in[9];
    const float* w3  = (const float*)d_in[10];
    const float* as3 = (const float*)d_in[11];
    const float* ad3 = (const float*)d_in[12];
    const float* b3  = (const float*)d_in[13];
    const float* wn  = (const float*)d_in[14];
    const float* bn  = (const float*)d_in[15];
    const float* wg  = (const float*)d_in[16];
    const float* bg  = (const float*)d_in[17];
    const float* wv  = (const float*)d_in[18];
    const float* bv  = (const float*)d_in[19];
    float* out = (float*)d_out;

    float *bufA, *bufB, *sA, *EsA, *Es2A, *dA, *EdA, *Ed2A, *gsm, *z2p;
    u32* bits;
    cudaGetSymbolAddress((void**)&bufA, g_bufA);
    cudaGetSymbolAddress((void**)&bufB, g_bufB);
    cudaGetSymbolAddress((void**)&sA,   g_s);
    cudaGetSymbolAddress((void**)&EsA,  g_Es);
    cudaGetSymbolAddress((void**)&Es2A, g_Es2);
    cudaGetSymbolAddress((void**)&dA,   g_d);
    cudaGetSymbolAddress((void**)&EdA,  g_Ed);
    cudaGetSymbolAddress((void**)&Ed2A, g_Ed2);
    cudaGetSymbolAddress((void**)&bits, g_bits);
    cudaGetSymbolAddress((void**)&gsm,  g_gsum);
    cudaGetSymbolAddress((void**)&z2p,  g_z2);

    const int M = BATCH * NT;

    pack_adj_kernel<<<M, 32>>>(adj, bits);

    // layer 1: 64 -> 4x64
    gemm_xwT<<<dim3(M / 128, 256 / 64), 256>>>(xin, w1, bufA, M, 64, 256);
    scores_kernel<<<(M * 32) / 256, 256>>>(bufA, as1, ad1, sA, EsA, Es2A, dA, EdA, Ed2A, 4);
    agg_kernel<<<dim3(NT / 64, 4, BATCH), 256>>>(bufA, sA, EsA, Es2A, dA, EdA, Ed2A,
                                                 bits, b1, bufB, 4);

    // layer 2: 4x64 -> 4x64
    gemm_xwT<<<dim3(M / 128, 256 / 64), 256>>>(bufB, w2, bufA, M, 256, 256);
    scores_kernel<<<(M * 32) / 256, 256>>>(bufA, as2, ad2, sA, EsA, Es2A, dA, EdA, Ed2A, 4);
    agg_kernel<<<dim3(NT / 64, 4, BATCH), 256>>>(bufA, sA, EsA, Es2A, dA, EdA, Ed2A,
                                                 bits, b2, bufB, 4);

    // layer 3: 4x64 -> 64 (H=1)
    gemm_xwT<<<dim3(M / 128, 1), 256>>>(bufB, w3, bufA, M, 256, 64);
    scores_kernel<<<(M * 32) / 256, 256>>>(bufA, as3, ad3, sA, EsA, Es2A, dA, EdA, Ed2A, 1);
    agg_kernel<<<dim3(NT / 64, 1, BATCH), 256>>>(bufA, sA, EsA, Es2A, dA, EdA, Ed2A,
                                                 bits, b3, bufB, 1);

    // readout
    gsum_kernel<<<BATCH, 256>>>(bufB, gsm);
    z2_kernel<<<BATCH, 64>>>(gsm, wg, bg, wv, z2p);
    final_kernel<<<M / 64, 256>>>(bufB, wn, bn, wv, bv, z2p, out);
}

// round 3
// speedup vs baseline: 2.1311x; 2.1311x over previous
#include <cuda_runtime.h>
#include <cuda_bf16.h>
#include <cstdint>

#define BATCH 8
#define NT    1024
typedef unsigned long long ull;
typedef unsigned int u32;

// ---------------- scratch (__device__ globals; no allocation allowed) ------
__device__ __align__(16) float g_bufA[BATCH * NT * 256];
__device__ __align__(16) float g_bufB[BATCH * NT * 256];
// scores, laid out [h][b][node]
__device__ __align__(16) float  g_sj [4 * BATCH * NT];
__device__ __align__(16) float  g_Esj[4 * BATCH * NT];
__device__ __align__(16) float  g_Es2[4 * BATCH * NT];
__device__ __align__(16) float4 g_dpk[4 * BATCH * NT];
// pre-transposed bf16-split features [h][b][c=64][node=1024]
__device__ __align__(16) __nv_bfloat16 g_hThi[4 * BATCH * 64 * NT];
__device__ __align__(16) __nv_bfloat16 g_hTlo[4 * BATCH * 64 * NT];
__device__ __align__(16) u32   g_bits[BATCH * NT * (NT / 32)];
__device__ __align__(16) float g_gsum[BATCH * 64];
__device__ __align__(16) float g_z2[BATCH];

// ---------------- helpers --------------------------------------------------
__device__ __forceinline__ uint32_t smem_u32(const void* p) {
    uint32_t a;
    asm("{ .reg .u64 t; cvta.to.shared.u64 t, %1; cvt.u32.u64 %0, t; }" : "=r"(a) : "l"(p));
    return a;
}

__device__ __forceinline__ void ldsm4(u32* r, u32 addr) {
    asm volatile("ldmatrix.sync.aligned.m8n8.x4.shared.b16 {%0,%1,%2,%3}, [%4];"
                 : "=r"(r[0]), "=r"(r[1]), "=r"(r[2]), "=r"(r[3]) : "r"(addr));
}

__device__ __forceinline__ void mma16816(float* c, const u32* a, u32 b0, u32 b1) {
    asm volatile(
        "mma.sync.aligned.m16n8k16.row.col.f32.bf16.bf16.f32 "
        "{%0,%1,%2,%3}, {%4,%5,%6,%7}, {%8,%9}, {%0,%1,%2,%3};"
        : "+f"(c[0]), "+f"(c[1]), "+f"(c[2]), "+f"(c[3])
        : "r"(a[0]), "r"(a[1]), "r"(a[2]), "r"(a[3]), "r"(b0), "r"(b1));
}

__device__ __forceinline__ float edgef(float s, float Es, float Es2, float4 dp, u32 bit) {
    float e = (s + dp.x > 0.f) ? Es * dp.y : Es2 * dp.z;
    return bit ? e : 0.f;
}

__device__ __forceinline__ void split2(float ex, float ey, u32& hi, u32& lo) {
    __nv_bfloat16 hx = __float2bfloat16_rn(ex);
    __nv_bfloat16 hy = __float2bfloat16_rn(ey);
    hi = (u32)__bfloat16_as_ushort(hx) | ((u32)__bfloat16_as_ushort(hy) << 16);
    __nv_bfloat16 lx = __float2bfloat16_rn(ex - __bfloat162float(hx));
    __nv_bfloat16 ly = __float2bfloat16_rn(ey - __bfloat162float(hy));
    lo = (u32)__bfloat16_as_ushort(lx) | ((u32)__bfloat16_as_ushort(ly) << 16);
}

// ---------------- adj bit packing (with self loops) ------------------------
__global__ void pack_adj_kernel(const int* __restrict__ adj, u32* __restrict__ bits) {
    int row = blockIdx.x;                 // b*NT + i
    int lane = threadIdx.x;               // 32 threads
    int i = row & (NT - 1);
    const int* arow = adj + (size_t)row * NT;
    for (int w = 0; w < 32; w++) {
        int j = w * 32 + lane;
        int v = arow[j];
        unsigned m = __ballot_sync(0xffffffffu, (v > 0) || (j == i));
        if (lane == 0) bits[row * 32 + w] = m;
    }
}

// ---------------- feature GEMM: Y[M,Nc] = X[M,K] @ W[Nc,K]^T ---------------
__global__ __launch_bounds__(256) void gemm_xwT(
    const float* __restrict__ X, const float* __restrict__ W,
    float* __restrict__ Y, int M, int K, int Nc)
{
    __shared__ float Xs[128][16];
    __shared__ float Ws[64][17];
    int tid = threadIdx.x;
    int m0 = blockIdx.x * 128, n0 = blockIdx.y * 64;
    int tx = tid & 15;
    int ty = tid >> 4;
    float acc[8][4];
#pragma unroll
    for (int r = 0; r < 8; r++)
#pragma unroll
        for (int c = 0; c < 4; c++) acc[r][c] = 0.f;

    for (int k0 = 0; k0 < K; k0 += 16) {
#pragma unroll
        for (int l = 0; l < 2; l++) {
            int f = tid + l * 256;
            int row = f >> 2;
            int kc = (f & 3) * 4;
            float4 v = *(const float4*)&X[(size_t)(m0 + row) * K + k0 + kc];
            Xs[row][kc] = v.x; Xs[row][kc + 1] = v.y;
            Xs[row][kc + 2] = v.z; Xs[row][kc + 3] = v.w;
        }
        {
            int row = tid >> 2;
            int kc = (tid & 3) * 4;
            float4 v = *(const float4*)&W[(size_t)(n0 + row) * K + k0 + kc];
            Ws[row][kc] = v.x; Ws[row][kc + 1] = v.y;
            Ws[row][kc + 2] = v.z; Ws[row][kc + 3] = v.w;
        }
        __syncthreads();
#pragma unroll
        for (int kk = 0; kk < 16; kk++) {
            float a[8], bb[4];
#pragma unroll
            for (int r = 0; r < 8; r++) a[r] = Xs[ty * 8 + r][kk];
#pragma unroll
            for (int c = 0; c < 4; c++) bb[c] = Ws[tx * 4 + c][kk];
#pragma unroll
            for (int r = 0; r < 8; r++)
#pragma unroll
                for (int c = 0; c < 4; c++) acc[r][c] += a[r] * bb[c];
        }
        __syncthreads();
    }
#pragma unroll
    for (int r = 0; r < 8; r++)
#pragma unroll
        for (int c = 0; c < 4; c++)
            Y[(size_t)(m0 + ty * 8 + r) * Nc + n0 + tx * 4 + c] = acc[r][c];
}

// ---------------- attention score precompute -------------------------------
// outputs laid out [h][b][node]
__global__ void scores_kernel(
    const float* __restrict__ feat,
    const float* __restrict__ a_src, const float* __restrict__ a_dst,
    float* __restrict__ sj, float* __restrict__ Esj, float* __restrict__ Es2j,
    float4* __restrict__ dpk, int H)
{
    int gtid = blockIdx.x * blockDim.x + threadIdx.x;
    int wid = gtid >> 5;
    int lane = threadIdx.x & 31;
    if (wid >= BATCH * NT) return;
    const float* frow = feat + (size_t)wid * H * 64;
    for (int h = 0; h < H; h++) {
        float f0 = frow[h * 64 + lane];
        float f1 = frow[h * 64 + 32 + lane];
        float s = f0 * a_src[h * 64 + lane] + f1 * a_src[h * 64 + 32 + lane];
        float d = f0 * a_dst[h * 64 + lane] + f1 * a_dst[h * 64 + 32 + lane];
#pragma unroll
        for (int o = 16; o > 0; o >>= 1) {
            s += __shfl_xor_sync(0xffffffffu, s, o);
            d += __shfl_xor_sync(0xffffffffu, d, o);
        }
        if (lane == 0) {
            int idx = h * (BATCH * NT) + wid;
            sj[idx]   = s;
            Esj[idx]  = __expf(s);
            Es2j[idx] = __expf(0.2f * s);
            dpk[idx]  = make_float4(d, __expf(d), __expf(0.2f * d), 0.f);
        }
    }
}

// ---------------- transpose + bf16-split features --------------------------
// feat [b][node][H*64] f32  ->  hThi/hTlo [h][b][c=64][node=NT] bf16
__global__ __launch_bounds__(256) void transpose_kernel(
    const float* __restrict__ feat,
    __nv_bfloat16* __restrict__ hhi, __nv_bfloat16* __restrict__ hlo, int H)
{
    __shared__ float ts[64][65];
    int tid = threadIdx.x;
    int jt = blockIdx.x, h = blockIdx.y, b = blockIdx.z;
    int j0 = jt * 64;
    int fs = H * 64;
    const float* fb = feat + (size_t)(b * NT + j0) * fs + h * 64;
#pragma unroll
    for (int l = 0; l < 4; l++) {
        int f = tid + l * 256;
        int j = f >> 4, c4 = f & 15;
        float4 v = *(const float4*)(fb + (size_t)j * fs + c4 * 4);
        ts[j][c4 * 4] = v.x; ts[j][c4 * 4 + 1] = v.y;
        ts[j][c4 * 4 + 2] = v.z; ts[j][c4 * 4 + 3] = v.w;
    }
    __syncthreads();
    int c = tid >> 2, q = tid & 3;
    size_t gof = ((size_t)((h * BATCH + b) * 64 + c)) * NT + j0 + q * 16;
    u32 hw[8], lw[8];
#pragma unroll
    for (int p = 0; p < 8; p++) {
        float x0 = ts[q * 16 + 2 * p][c];
        float x1 = ts[q * 16 + 2 * p + 1][c];
        __nv_bfloat16 b0 = __float2bfloat16_rn(x0), b1 = __float2bfloat16_rn(x1);
        float l0 = x0 - __bfloat162float(b0), l1 = x1 - __bfloat162float(b1);
        __nv_bfloat16 c0 = __float2bfloat16_rn(l0), c1 = __float2bfloat16_rn(l1);
        hw[p] = (u32)__bfloat16_as_ushort(b0) | ((u32)__bfloat16_as_ushort(b1) << 16);
        lw[p] = (u32)__bfloat16_as_ushort(c0) | ((u32)__bfloat16_as_ushort(c1) << 16);
    }
    *(uint4*)(hhi + gof)     = make_uint4(hw[0], hw[1], hw[2], hw[3]);
    *(uint4*)(hhi + gof + 8) = make_uint4(hw[4], hw[5], hw[6], hw[7]);
    *(uint4*)(hlo + gof)     = make_uint4(lw[0], lw[1], lw[2], lw[3]);
    *(uint4*)(hlo + gof + 8) = make_uint4(lw[4], lw[5], lw[6], lw[7]);
}

// ---------------- HMMA aggregation -----------------------------------------
// grid (NT/128, H, B), 256 threads = 8 warps; warp w owns rows w*16..w*16+15.
// D[i,c] = sum_j E[i,j]*h[j,c] via mma.sync bf16 with hi/lo split (3 passes).
// E fragments are computed directly in registers in the A-fragment layout.
__global__ __launch_bounds__(256) void agg_mma_kernel(
    const __nv_bfloat16* __restrict__ hThi, const __nv_bfloat16* __restrict__ hTlo,
    const float* __restrict__ sjA, const float* __restrict__ EsA,
    const float* __restrict__ Es2A, const float4* __restrict__ dpk,
    const ull* __restrict__ bits64,
    const float* __restrict__ bias, float* __restrict__ xout, int H)
{
    __shared__ __align__(16) __nv_bfloat16 sh_h[2][2][64 * 64]; // [buf][hi/lo]
    __shared__ float sh_sc[2][3][64];                            // [buf][s/Es/Es2]

    const int tid = threadIdx.x;
    const int w = tid >> 5, l = tid & 31;
    const int b = blockIdx.z, h = blockIdx.y;
    const int i0 = blockIdx.x * 128;
    const int hb = h * BATCH + b;
    const int fs = H * 64;

    // row pair this thread accumulates (within 128-row strip)
    const int r0 = w * 16 + (l >> 2);
    const int r1 = r0 + 8;
    const float4 dp0 = dpk[hb * NT + i0 + r0];
    const float4 dp1 = dpk[hb * NT + i0 + r1];
    const ull* mrow0 = bits64 + (size_t)(b * NT + i0 + r0) * 16;
    const ull* mrow1 = bits64 + (size_t)(b * NT + i0 + r1) * 16;

    const float* sjp = sjA + hb * NT;
    const float* Esp = EsA + hb * NT;
    const float* Fsp = Es2A + hb * NT;
    const __nv_bfloat16* hhp = hThi + (size_t)hb * 64 * NT;
    const __nv_bfloat16* hlp = hTlo + (size_t)hb * 64 * NT;

    // h-tile staging mapping: thread handles chunks tid and tid+256 (16B each)
    const int c0 = tid >> 3, jc = tid & 7;
    auto swz = [](u32 off) { return off ^ ((off >> 3) & 0x70); };
    const u32 st0 = swz((u32)(c0 * 128 + jc * 16));
    const u32 st1 = swz((u32)((c0 + 32) * 128 + jc * 16));
    // score staging
    const float* scsrc = (tid < 64) ? sjp : (tid < 128 ? Esp : Fsp);
    const int scidx = tid & 63;

    float acc[8][4];
#pragma unroll
    for (int ng = 0; ng < 8; ng++)
#pragma unroll
        for (int r = 0; r < 4; r++) acc[ng][r] = 0.f;
    float rs0 = 0.f, rs1 = 0.f;

    uint4 pvh0, pvh1, pvl0, pvl1;
    float psc = 0.f;

    auto ldg_tile = [&](int t) {
        int j0 = t * 64;
        pvh0 = *(const uint4*)(hhp + (size_t)c0 * NT + j0 + jc * 8);
        pvh1 = *(const uint4*)(hhp + (size_t)(c0 + 32) * NT + j0 + jc * 8);
        pvl0 = *(const uint4*)(hlp + (size_t)c0 * NT + j0 + jc * 8);
        pvl1 = *(const uint4*)(hlp + (size_t)(c0 + 32) * NT + j0 + jc * 8);
        if (tid < 192) psc = scsrc[j0 + scidx];
    };

    ldg_tile(0);

    const u32 su_hi[2] = { smem_u32(sh_h[0][0]), smem_u32(sh_h[1][0]) };
    const u32 su_lo[2] = { smem_u32(sh_h[0][1]), smem_u32(sh_h[1][1]) };

    for (int t = 0; t < 16; t++) {
        int buf = t & 1;
        // stage
        *(uint4*)((char*)sh_h[buf][0] + st0) = pvh0;
        *(uint4*)((char*)sh_h[buf][0] + st1) = pvh1;
        *(uint4*)((char*)sh_h[buf][1] + st0) = pvl0;
        *(uint4*)((char*)sh_h[buf][1] + st1) = pvl1;
        if (tid < 192) sh_sc[buf][tid >> 6][scidx] = psc;
        __syncthreads();
        if (t < 15) ldg_tile(t + 1);

        const float* scS = sh_sc[buf][0];
        const float* scE = sh_sc[buf][1];
        const float* scF = sh_sc[buf][2];
        const ull m0 = mrow0[t];
        const ull m1 = mrow1[t];

#pragma unroll
        for (int q = 0; q < 4; q++) {
            const int jA = q * 16 + 2 * (l & 3);
            float s0 = scS[jA], s1 = scS[jA + 1], s2 = scS[jA + 8], s3 = scS[jA + 9];
            float E0 = scE[jA], E1 = scE[jA + 1], E2 = scE[jA + 8], E3 = scE[jA + 9];
            float F0 = scF[jA], F1 = scF[jA + 1], F2 = scF[jA + 8], F3 = scF[jA + 9];

            u32 ahi[4], alo[4];
            // row r0
            {
                float eA = edgef(s0, E0, F0, dp0, (u32)(m0 >> jA) & 1u);
                float eB = edgef(s1, E1, F1, dp0, (u32)(m0 >> (jA + 1)) & 1u);
                float eC = edgef(s2, E2, F2, dp0, (u32)(m0 >> (jA + 8)) & 1u);
                float eD = edgef(s3, E3, F3, dp0, (u32)(m0 >> (jA + 9)) & 1u);
                rs0 += (eA + eB) + (eC + eD);
                split2(eA, eB, ahi[0], alo[0]);
                split2(eC, eD, ahi[2], alo[2]);
            }
            // row r1
            {
                float eA = edgef(s0, E0, F0, dp1, (u32)(m1 >> jA) & 1u);
                float eB = edgef(s1, E1, F1, dp1, (u32)(m1 >> (jA + 1)) & 1u);
                float eC = edgef(s2, E2, F2, dp1, (u32)(m1 >> (jA + 8)) & 1u);
                float eD = edgef(s3, E3, F3, dp1, (u32)(m1 >> (jA + 9)) & 1u);
                rs1 += (eA + eB) + (eC + eD);
                split2(eA, eB, ahi[1], alo[1]);
                split2(eC, eD, ahi[3], alo[3]);
            }

            // B fragments via ldmatrix (layout [n][k], k-contiguous, SW swizzled)
            u32 bh[16], bl[16];
            const int sub = l >> 3;
            const int brow = (l & 7) + ((sub >> 1) << 3);
            const int bchunk = 2 * q + (sub & 1);
#pragma unroll
            for (int g = 0; g < 4; g++) {
                u32 off = swz((u32)((g * 16 + brow) * 128 + bchunk * 16));
                ldsm4(bh + g * 4, su_hi[buf] + off);
                ldsm4(bl + g * 4, su_lo[buf] + off);
            }
#pragma unroll
            for (int g = 0; g < 4; g++) {
#pragma unroll
                for (int m = 0; m < 2; m++) {
                    int ng = g * 2 + m;
                    u32 h0 = bh[g * 4 + 2 * m], h1 = bh[g * 4 + 2 * m + 1];
                    u32 l0 = bl[g * 4 + 2 * m], l1 = bl[g * 4 + 2 * m + 1];
                    mma16816(acc[ng], ahi, h0, h1);
                    mma16816(acc[ng], ahi, l0, l1);
                    mma16816(acc[ng], alo, h0, h1);
                }
            }
        }
        __syncthreads();
    }

    // rowsum reduce across the 4 lanes that share a row
    rs0 += __shfl_xor_sync(0xffffffffu, rs0, 1);
    rs0 += __shfl_xor_sync(0xffffffffu, rs0, 2);
    rs1 += __shfl_xor_sync(0xffffffffu, rs1, 1);
    rs1 += __shfl_xor_sync(0xffffffffu, rs1, 2);
    float rinv0 = 1.0f / rs0;
    float rinv1 = 1.0f / rs1;

    float* orow0 = xout + (size_t)(b * NT + i0 + r0) * fs + h * 64;
    float* orow1 = xout + (size_t)(b * NT + i0 + r1) * fs + h * 64;
#pragma unroll
    for (int ng = 0; ng < 8; ng++) {
        int col = ng * 8 + 2 * (l & 3);
        float2 bb = *(const float2*)(bias + h * 64 + col);
        float2 o0, o1;
        o0.x = fmaxf(acc[ng][0] * rinv0 + bb.x, 0.f);
        o0.y = fmaxf(acc[ng][1] * rinv0 + bb.y, 0.f);
        o1.x = fmaxf(acc[ng][2] * rinv1 + bb.x, 0.f);
        o1.y = fmaxf(acc[ng][3] * rinv1 + bb.y, 0.f);
        *(float2*)(orow0 + col) = o0;
        *(float2*)(orow1 + col) = o1;
    }
}

// ---------------- readout --------------------------------------------------
__global__ void gsum_kernel(const float* __restrict__ x, float* __restrict__ g) {
    int b = blockIdx.x;
    int tid = threadIdx.x;
    int c = tid & 63, nq = tid >> 6;
    float acc = 0.f;
    for (int n = nq; n < NT; n += 4) acc += x[((size_t)b * NT + n) * 64 + c];
    __shared__ float sm[256];
    sm[tid] = acc;
    __syncthreads();
    if (tid < 64) g[b * 64 + tid] = sm[tid] + sm[64 + tid] + sm[128 + tid] + sm[192 + tid];
}

__global__ void z2_kernel(const float* __restrict__ g, const float* __restrict__ wg,
                          const float* __restrict__ bg, const float* __restrict__ wv,
                          float* __restrict__ z2) {
    int b = blockIdx.x;
    int c = threadIdx.x;
    float acc = bg[c];
    for (int k = 0; k < 64; k++) acc += g[b * 64 + k] * wg[c * 64 + k];
    float y = fmaxf(acc, 0.f) * wv[64 + c];
    __shared__ float sm[64];
    sm[c] = y;
    __syncthreads();
    if (c == 0) {
        float t = 0.f;
        for (int k = 0; k < 64; k++) t += sm[k];
        z2[b] = t;
    }
}

__global__ __launch_bounds__(256) void final_kernel(
    const float* __restrict__ x,
    const float* __restrict__ wn, const float* __restrict__ bn,
    const float* __restrict__ wv, const float* __restrict__ bv,
    const float* __restrict__ z2, float* __restrict__ out)
{
    __shared__ float wns[64][65];
    __shared__ float bns[64], wvs[64];
    int tid = threadIdx.x;
#pragma unroll
    for (int l = 0; l < 16; l++) {
        int f = tid + l * 256;
        wns[f >> 6][f & 63] = wn[f];
    }
    if (tid < 64) { bns[tid] = bn[tid]; wvs[tid] = wv[tid]; }
    __syncthreads();

    int row = blockIdx.x * 64 + (tid >> 2);
    int q = tid & 3;
    float xr[64];
#pragma unroll
    for (int k = 0; k < 64; k++) xr[k] = x[(size_t)row * 64 + k];
    float y = 0.f;
    for (int c16 = 0; c16 < 16; c16++) {
        int c = q * 16 + c16;
        float acc = bns[c];
#pragma unroll
        for (int k = 0; k < 64; k++) acc += xr[k] * wns[c][k];
        y += fmaxf(acc, 0.f) * wvs[c];
    }
    y += __shfl_xor_sync(0xffffffffu, y, 1);
    y += __shfl_xor_sync(0xffffffffu, y, 2);
    if (q == 0) out[row] = y + z2[row >> 10] + bv[0];
}

// ---------------- launch ----------------------------------------------------
extern "C" void kernel_launch(void* const* d_in, const int* in_sizes, int n_in,
                              void* d_out, int out_size)
{
    const float* xin = (const float*)d_in[0];
    const int*   adj = (const int*)d_in[1];
    const float* w1  = (const float*)d_in[2];
    const float* as1 = (const float*)d_in[3];
    const float* ad1 = (const float*)d_in[4];
    const float* b1  = (const float*)d_in[5];
    const float* w2  = (const float*)d_in[6];
    const float* as2 = (const float*)d_in[7];
    const float* ad2 = (const float*)d_in[8];
    const float* b2  = (const float*)d_in[9];
    const float* w3  = (const float*)d_in[10];
    const float* as3 = (const float*)d_in[11];
    const float* ad3 = (const float*)d_in[12];
    const float* b3  = (const float*)d_in[13];
    const float* wn  = (const float*)d_in[14];
    const float* bn  = (const float*)d_in[15];
    const float* wg  = (const float*)d_in[16];
    const float* bg  = (const float*)d_in[17];
    const float* wv  = (const float*)d_in[18];
    const float* bv  = (const float*)d_in[19];
    float* out = (float*)d_out;

    float *bufA, *bufB, *sA, *EsA, *Es2A, *gsm, *z2p;
    float4* dpk;
    __nv_bfloat16 *hhi, *hlo;
    u32* bits;
    cudaGetSymbolAddress((void**)&bufA, g_bufA);
    cudaGetSymbolAddress((void**)&bufB, g_bufB);
    cudaGetSymbolAddress((void**)&sA,   g_sj);
    cudaGetSymbolAddress((void**)&EsA,  g_Esj);
    cudaGetSymbolAddress((void**)&Es2A, g_Es2);
    cudaGetSymbolAddress((void**)&dpk,  g_dpk);
    cudaGetSymbolAddress((void**)&hhi,  g_hThi);
    cudaGetSymbolAddress((void**)&hlo,  g_hTlo);
    cudaGetSymbolAddress((void**)&bits, g_bits);
    cudaGetSymbolAddress((void**)&gsm,  g_gsum);
    cudaGetSymbolAddress((void**)&z2p,  g_z2);

    const int M = BATCH * NT;
    const ull* bits64 = (const ull*)bits;

    pack_adj_kernel<<<M, 32>>>(adj, bits);

    // layer 1: 64 -> 4x64
    gemm_xwT<<<dim3(M / 128, 4), 256>>>(xin, w1, bufA, M, 64, 256);
    scores_kernel<<<(M * 32) / 256, 256>>>(bufA, as1, ad1, sA, EsA, Es2A, dpk, 4);
    transpose_kernel<<<dim3(16, 4, BATCH), 256>>>(bufA, hhi, hlo, 4);
    agg_mma_kernel<<<dim3(NT / 128, 4, BATCH), 256>>>(
        hhi, hlo, sA, EsA, Es2A, dpk, bits64, b1, bufB, 4);

    // layer 2: 4x64 -> 4x64
    gemm_xwT<<<dim3(M / 128, 4), 256>>>(bufB, w2, bufA, M, 256, 256);
    scores_kernel<<<(M * 32) / 256, 256>>>(bufA, as2, ad2, sA, EsA, Es2A, dpk, 4);
    transpose_kernel<<<dim3(16, 4, BATCH), 256>>>(bufA, hhi, hlo, 4);
    agg_mma_kernel<<<dim3(NT / 128, 4, BATCH), 256>>>(
        hhi, hlo, sA, EsA, Es2A, dpk, bits64, b2, bufB, 4);

    // layer 3: 4x64 -> 64 (H=1)
    gemm_xwT<<<dim3(M / 128, 1), 256>>>(bufB, w3, bufA, M, 256, 64);
    scores_kernel<<<(M * 32) / 256, 256>>>(bufA, as3, ad3, sA, EsA, Es2A, dpk, 1);
    transpose_kernel<<<dim3(16, 1, BATCH), 256>>>(bufA, hhi, hlo, 1);
    agg_mma_kernel<<<dim3(NT / 128, 1, BATCH), 256>>>(
        hhi, hlo, sA, EsA, Es2A, dpk, bits64, b3, bufB, 1);

    // readout
    gsum_kernel<<<BATCH, 256>>>(bufB, gsm);
    z2_kernel<<<BATCH, 64>>>(gsm, wg, bg, wv, z2p);
    final_kernel<<<M / 64, 256>>>(bufB, wn, bn, wv, bv, z2p, out);
}

// round 6
// speedup vs baseline: 2.6721x; 1.2539x over previous
#include <cuda_runtime.h>
#include <cuda_bf16.h>
#include <cstdint>

#define BATCH 8
#define NT    1024
typedef unsigned long long ull;
typedef unsigned int u32;

// ---------------- scratch (__device__ globals; no allocation allowed) ------
__device__ __align__(16) float g_bufA[BATCH * NT * 256];
__device__ __align__(16) float g_bufB[BATCH * NT * 256];
// scores, laid out [h][b][node]
__device__ __align__(16) float  g_sj [4 * BATCH * NT];
__device__ __align__(16) float  g_Esj[4 * BATCH * NT];
__device__ __align__(16) float  g_Es2[4 * BATCH * NT];
__device__ __align__(16) float4 g_dpk[4 * BATCH * NT];
// pre-transposed bf16-split features [h][b][c=64][node=1024]
__device__ __align__(16) __nv_bfloat16 g_hThi[4 * BATCH * 64 * NT];
__device__ __align__(16) __nv_bfloat16 g_hTlo[4 * BATCH * 64 * NT];
__device__ __align__(16) u32   g_bits[BATCH * NT * (NT / 32)];
__device__ __align__(16) float g_gsum[BATCH * 64];
__device__ __align__(16) float g_z2[BATCH];

// ---------------- helpers --------------------------------------------------
__device__ __forceinline__ uint32_t smem_u32(const void* p) {
    uint32_t a;
    asm("{ .reg .u64 t; cvta.to.shared.u64 t, %1; cvt.u32.u64 %0, t; }" : "=r"(a) : "l"(p));
    return a;
}

__device__ __forceinline__ void ldsm4(u32* r, u32 addr) {
    asm volatile("ldmatrix.sync.aligned.m8n8.x4.shared.b16 {%0,%1,%2,%3}, [%4];"
                 : "=r"(r[0]), "=r"(r[1]), "=r"(r[2]), "=r"(r[3]) : "r"(addr));
}

__device__ __forceinline__ void mma16816(float* c, const u32* a, u32 b0, u32 b1) {
    asm volatile(
        "mma.sync.aligned.m16n8k16.row.col.f32.bf16.bf16.f32 "
        "{%0,%1,%2,%3}, {%4,%5,%6,%7}, {%8,%9}, {%0,%1,%2,%3};"
        : "+f"(c[0]), "+f"(c[1]), "+f"(c[2]), "+f"(c[3])
        : "r"(a[0]), "r"(a[1]), "r"(a[2]), "r"(a[3]), "r"(b0), "r"(b1));
}

__device__ __forceinline__ float edgef(float s, float Es, float Es2, float4 dp, u32 bit) {
    float e = (s + dp.x > 0.f) ? Es * dp.y : Es2 * dp.z;
    return bit ? e : 0.f;
}

// pack two fp32 into bf16x2 (lower = ex, upper = ey) in one cvt
__device__ __forceinline__ u32 packbf2(float ex, float ey) {
    u32 r;
    asm("cvt.rn.bf16x2.f32 %0, %1, %2;" : "=r"(r) : "f"(ey), "f"(ex));
    return r;
}

// sum of the two bf16 values in a packed word, as fp32 (exact widening)
__device__ __forceinline__ float sum2bf(u32 p) {
    float a = __uint_as_float(p << 16);
    float b = __uint_as_float(p & 0xffff0000u);
    return a + b;
}

// ---------------- adj bit packing (with self loops) ------------------------
__global__ void pack_adj_kernel(const int* __restrict__ adj, u32* __restrict__ bits) {
    int row = blockIdx.x;                 // b*NT + i
    int lane = threadIdx.x;               // 32 threads
    int i = row & (NT - 1);
    const int* arow = adj + (size_t)row * NT;
    for (int w = 0; w < 32; w++) {
        int j = w * 32 + lane;
        int v = arow[j];
        unsigned m = __ballot_sync(0xffffffffu, (v > 0) || (j == i));
        if (lane == 0) bits[row * 32 + w] = m;
    }
}

// ---------------- feature GEMM: Y[M,Nc] = X[M,K] @ W[Nc,K]^T ---------------
__global__ __launch_bounds__(256) void gemm_xwT(
    const float* __restrict__ X, const float* __restrict__ W,
    float* __restrict__ Y, int M, int K, int Nc)
{
    __shared__ float Xs[128][16];
    __shared__ float Ws[64][17];
    int tid = threadIdx.x;
    int m0 = blockIdx.x * 128, n0 = blockIdx.y * 64;
    int tx = tid & 15;
    int ty = tid >> 4;
    float acc[8][4];
#pragma unroll
    for (int r = 0; r < 8; r++)
#pragma unroll
        for (int c = 0; c < 4; c++) acc[r][c] = 0.f;

    for (int k0 = 0; k0 < K; k0 += 16) {
#pragma unroll
        for (int l = 0; l < 2; l++) {
            int f = tid + l * 256;
            int row = f >> 2;
            int kc = (f & 3) * 4;
            float4 v = *(const float4*)&X[(size_t)(m0 + row) * K + k0 + kc];
            Xs[row][kc] = v.x; Xs[row][kc + 1] = v.y;
            Xs[row][kc + 2] = v.z; Xs[row][kc + 3] = v.w;
        }
        {
            int row = tid >> 2;
            int kc = (tid & 3) * 4;
            float4 v = *(const float4*)&W[(size_t)(n0 + row) * K + k0 + kc];
            Ws[row][kc] = v.x; Ws[row][kc + 1] = v.y;
            Ws[row][kc + 2] = v.z; Ws[row][kc + 3] = v.w;
        }
        __syncthreads();
#pragma unroll
        for (int kk = 0; kk < 16; kk++) {
            float a[8], bb[4];
#pragma unroll
            for (int r = 0; r < 8; r++) a[r] = Xs[ty * 8 + r][kk];
#pragma unroll
            for (int c = 0; c < 4; c++) bb[c] = Ws[tx * 4 + c][kk];
#pragma unroll
            for (int r = 0; r < 8; r++)
#pragma unroll
                for (int c = 0; c < 4; c++) acc[r][c] += a[r] * bb[c];
        }
        __syncthreads();
    }
#pragma unroll
    for (int r = 0; r < 8; r++)
#pragma unroll
        for (int c = 0; c < 4; c++)
            Y[(size_t)(m0 + ty * 8 + r) * Nc + n0 + tx * 4 + c] = acc[r][c];
}

// ---------------- attention score precompute -------------------------------
// outputs laid out [h][b][node]
__global__ void scores_kernel(
    const float* __restrict__ feat,
    const float* __restrict__ a_src, const float* __restrict__ a_dst,
    float* __restrict__ sj, float* __restrict__ Esj, float* __restrict__ Es2j,
    float4* __restrict__ dpk, int H)
{
    int gtid = blockIdx.x * blockDim.x + threadIdx.x;
    int wid = gtid >> 5;
    int lane = threadIdx.x & 31;
    if (wid >= BATCH * NT) return;
    const float* frow = feat + (size_t)wid * H * 64;
    for (int h = 0; h < H; h++) {
        float f0 = frow[h * 64 + lane];
        float f1 = frow[h * 64 + 32 + lane];
        float s = f0 * a_src[h * 64 + lane] + f1 * a_src[h * 64 + 32 + lane];
        float d = f0 * a_dst[h * 64 + lane] + f1 * a_dst[h * 64 + 32 + lane];
#pragma unroll
        for (int o = 16; o > 0; o >>= 1) {
            s += __shfl_xor_sync(0xffffffffu, s, o);
            d += __shfl_xor_sync(0xffffffffu, d, o);
        }
        if (lane == 0) {
            int idx = h * (BATCH * NT) + wid;
            sj[idx]   = s;
            Esj[idx]  = __expf(s);
            Es2j[idx] = __expf(0.2f * s);
            dpk[idx]  = make_float4(d, __expf(d), __expf(0.2f * d), 0.f);
        }
    }
}

// ---------------- transpose + bf16-split features --------------------------
// feat [b][node][H*64] f32  ->  hThi/hTlo [h][b][c=64][node=NT] bf16
__global__ __launch_bounds__(256) void transpose_kernel(
    const float* __restrict__ feat,
    __nv_bfloat16* __restrict__ hhi, __nv_bfloat16* __restrict__ hlo, int H)
{
    __shared__ float ts[64][65];
    int tid = threadIdx.x;
    int jt = blockIdx.x, h = blockIdx.y, b = blockIdx.z;
    int j0 = jt * 64;
    int fs = H * 64;
    const float* fb = feat + (size_t)(b * NT + j0) * fs + h * 64;
#pragma unroll
    for (int l = 0; l < 4; l++) {
        int f = tid + l * 256;
        int j = f >> 4, c4 = f & 15;
        float4 v = *(const float4*)(fb + (size_t)j * fs + c4 * 4);
        ts[j][c4 * 4] = v.x; ts[j][c4 * 4 + 1] = v.y;
        ts[j][c4 * 4 + 2] = v.z; ts[j][c4 * 4 + 3] = v.w;
    }
    __syncthreads();
    int c = tid >> 2, q = tid & 3;
    size_t gof = ((size_t)((h * BATCH + b) * 64 + c)) * NT + j0 + q * 16;
    u32 hw[8], lw[8];
#pragma unroll
    for (int p = 0; p < 8; p++) {
        float x0 = ts[q * 16 + 2 * p][c];
        float x1 = ts[q * 16 + 2 * p + 1][c];
        __nv_bfloat16 b0 = __float2bfloat16_rn(x0), b1 = __float2bfloat16_rn(x1);
        float l0 = x0 - __bfloat162float(b0), l1 = x1 - __bfloat162float(b1);
        __nv_bfloat16 c0 = __float2bfloat16_rn(l0), c1 = __float2bfloat16_rn(l1);
        hw[p] = (u32)__bfloat16_as_ushort(b0) | ((u32)__bfloat16_as_ushort(b1) << 16);
        lw[p] = (u32)__bfloat16_as_ushort(c0) | ((u32)__bfloat16_as_ushort(c1) << 16);
    }
    *(uint4*)(hhi + gof)     = make_uint4(hw[0], hw[1], hw[2], hw[3]);
    *(uint4*)(hhi + gof + 8) = make_uint4(hw[4], hw[5], hw[6], hw[7]);
    *(uint4*)(hlo + gof)     = make_uint4(lw[0], lw[1], lw[2], lw[3]);
    *(uint4*)(hlo + gof + 8) = make_uint4(lw[4], lw[5], lw[6], lw[7]);
}

// ---------------- HMMA aggregation -----------------------------------------
// grid (NT/128, H, B), 256 threads = 8 warps; warp w owns rows w*16..w*16+15.
// D[i,c] = sum_j E[i,j]*h[j,c] via mma.sync bf16.
// E quantized to bf16 (one A pass); B split hi/lo (2 passes).
// Rowsum accumulated from the QUANTIZED bf16 weights so the correlated
// per-row rounding of E cancels exactly in the normalization.
__global__ __launch_bounds__(256) void agg_mma_kernel(
    const __nv_bfloat16* __restrict__ hThi, const __nv_bfloat16* __restrict__ hTlo,
    const float* __restrict__ sjA, const float* __restrict__ EsA,
    const float* __restrict__ Es2A, const float4* __restrict__ dpk,
    const ull* __restrict__ bits64,
    const float* __restrict__ bias, float* __restrict__ xout, int H)
{
    __shared__ __align__(16) __nv_bfloat16 sh_h[2][2][64 * 64]; // [buf][hi/lo]
    __shared__ float sh_sc[2][3][64];                            // [buf][s/Es/Es2]

    const int tid = threadIdx.x;
    const int w = tid >> 5, l = tid & 31;
    const int b = blockIdx.z, h = blockIdx.y;
    const int i0 = blockIdx.x * 128;
    const int hb = h * BATCH + b;
    const int fs = H * 64;

    // row pair this thread accumulates (within 128-row strip)
    const int r0 = w * 16 + (l >> 2);
    const int r1 = r0 + 8;
    const float4 dp0 = dpk[hb * NT + i0 + r0];
    const float4 dp1 = dpk[hb * NT + i0 + r1];
    const ull* mrow0 = bits64 + (size_t)(b * NT + i0 + r0) * 16;
    const ull* mrow1 = bits64 + (size_t)(b * NT + i0 + r1) * 16;

    const float* sjp = sjA + hb * NT;
    const float* Esp = EsA + hb * NT;
    const float* Fsp = Es2A + hb * NT;
    const __nv_bfloat16* hhp = hThi + (size_t)hb * 64 * NT;
    const __nv_bfloat16* hlp = hTlo + (size_t)hb * 64 * NT;

    // h-tile staging mapping: thread handles chunks tid and tid+256 (16B each)
    const int c0 = tid >> 3, jc = tid & 7;
    auto swz = [](u32 off) { return off ^ ((off >> 3) & 0x70); };
    const u32 st0 = swz((u32)(c0 * 128 + jc * 16));
    const u32 st1 = swz((u32)((c0 + 32) * 128 + jc * 16));
    // score staging
    const float* scsrc = (tid < 64) ? sjp : (tid < 128 ? Esp : Fsp);
    const int scidx = tid & 63;

    float acc[8][4];
#pragma unroll
    for (int ng = 0; ng < 8; ng++)
#pragma unroll
        for (int r = 0; r < 4; r++) acc[ng][r] = 0.f;
    float rs0 = 0.f, rs1 = 0.f;

    uint4 pvh0, pvh1, pvl0, pvl1;
    float psc = 0.f;

    auto ldg_tile = [&](int t) {
        int j0 = t * 64;
        pvh0 = *(const uint4*)(hhp + (size_t)c0 * NT + j0 + jc * 8);
        pvh1 = *(const uint4*)(hhp + (size_t)(c0 + 32) * NT + j0 + jc * 8);
        pvl0 = *(const uint4*)(hlp + (size_t)c0 * NT + j0 + jc * 8);
        pvl1 = *(const uint4*)(hlp + (size_t)(c0 + 32) * NT + j0 + jc * 8);
        if (tid < 192) psc = scsrc[j0 + scidx];
    };

    ldg_tile(0);

    const u32 su_hi[2] = { smem_u32(sh_h[0][0]), smem_u32(sh_h[1][0]) };
    const u32 su_lo[2] = { smem_u32(sh_h[0][1]), smem_u32(sh_h[1][1]) };

    for (int t = 0; t < 16; t++) {
        int buf = t & 1;
        // stage
        *(uint4*)((char*)sh_h[buf][0] + st0) = pvh0;
        *(uint4*)((char*)sh_h[buf][0] + st1) = pvh1;
        *(uint4*)((char*)sh_h[buf][1] + st0) = pvl0;
        *(uint4*)((char*)sh_h[buf][1] + st1) = pvl1;
        if (tid < 192) sh_sc[buf][tid >> 6][scidx] = psc;
        __syncthreads();
        if (t < 15) ldg_tile(t + 1);

        const float* scS = sh_sc[buf][0];
        const float* scE = sh_sc[buf][1];
        const float* scF = sh_sc[buf][2];
        const ull m0 = mrow0[t];
        const ull m1 = mrow1[t];

#pragma unroll
        for (int q = 0; q < 4; q++) {
            const int jA = q * 16 + 2 * (l & 3);
            float s0 = scS[jA], s1 = scS[jA + 1], s2 = scS[jA + 8], s3 = scS[jA + 9];
            float E0 = scE[jA], E1 = scE[jA + 1], E2 = scE[jA + 8], E3 = scE[jA + 9];
            float F0 = scF[jA], F1 = scF[jA + 1], F2 = scF[jA + 8], F3 = scF[jA + 9];

            u32 ahi[4];
            // row r0
            {
                float eA = edgef(s0, E0, F0, dp0, (u32)(m0 >> jA) & 1u);
                float eB = edgef(s1, E1, F1, dp0, (u32)(m0 >> (jA + 1)) & 1u);
                float eC = edgef(s2, E2, F2, dp0, (u32)(m0 >> (jA + 8)) & 1u);
                float eD = edgef(s3, E3, F3, dp0, (u32)(m0 >> (jA + 9)) & 1u);
                ahi[0] = packbf2(eA, eB);
                ahi[2] = packbf2(eC, eD);
                rs0 += sum2bf(ahi[0]) + sum2bf(ahi[2]);
            }
            // row r1
            {
                float eA = edgef(s0, E0, F0, dp1, (u32)(m1 >> jA) & 1u);
                float eB = edgef(s1, E1, F1, dp1, (u32)(m1 >> (jA + 1)) & 1u);
                float eC = edgef(s2, E2, F2, dp1, (u32)(m1 >> (jA + 8)) & 1u);
                float eD = edgef(s3, E3, F3, dp1, (u32)(m1 >> (jA + 9)) & 1u);
                ahi[1] = packbf2(eA, eB);
                ahi[3] = packbf2(eC, eD);
                rs1 += sum2bf(ahi[1]) + sum2bf(ahi[3]);
            }

            // B fragments via ldmatrix (layout [n][k], k-contiguous, SW swizzled)
            u32 bh[16], bl[16];
            const int sub = l >> 3;
            const int brow = (l & 7) + ((sub >> 1) << 3);
            const int bchunk = 2 * q + (sub & 1);
#pragma unroll
            for (int g = 0; g < 4; g++) {
                u32 off = swz((u32)((g * 16 + brow) * 128 + bchunk * 16));
                ldsm4(bh + g * 4, su_hi[buf] + off);
                ldsm4(bl + g * 4, su_lo[buf] + off);
            }
#pragma unroll
            for (int g = 0; g < 4; g++) {
#pragma unroll
                for (int m = 0; m < 2; m++) {
                    int ng = g * 2 + m;
                    u32 h0 = bh[g * 4 + 2 * m], h1 = bh[g * 4 + 2 * m + 1];
                    u32 l0 = bl[g * 4 + 2 * m], l1 = bl[g * 4 + 2 * m + 1];
                    mma16816(acc[ng], ahi, h0, h1);
                    mma16816(acc[ng], ahi, l0, l1);
                }
            }
        }
        __syncthreads();
    }

    // rowsum reduce across the 4 lanes that share a row
    rs0 += __shfl_xor_sync(0xffffffffu, rs0, 1);
    rs0 += __shfl_xor_sync(0xffffffffu, rs0, 2);
    rs1 += __shfl_xor_sync(0xffffffffu, rs1, 1);
    rs1 += __shfl_xor_sync(0xffffffffu, rs1, 2);
    float rinv0 = 1.0f / rs0;
    float rinv1 = 1.0f / rs1;

    float* orow0 = xout + (size_t)(b * NT + i0 + r0) * fs + h * 64;
    float* orow1 = xout + (size_t)(b * NT + i0 + r1) * fs + h * 64;
#pragma unroll
    for (int ng = 0; ng < 8; ng++) {
        int col = ng * 8 + 2 * (l & 3);
        float2 bb = *(const float2*)(bias + h * 64 + col);
        float2 o0, o1;
        o0.x = fmaxf(acc[ng][0] * rinv0 + bb.x, 0.f);
        o0.y = fmaxf(acc[ng][1] * rinv0 + bb.y, 0.f);
        o1.x = fmaxf(acc[ng][2] * rinv1 + bb.x, 0.f);
        o1.y = fmaxf(acc[ng][3] * rinv1 + bb.y, 0.f);
        *(float2*)(orow0 + col) = o0;
        *(float2*)(orow1 + col) = o1;
    }
}

// ---------------- readout --------------------------------------------------
__global__ void gsum_kernel(const float* __restrict__ x, float* __restrict__ g) {
    int b = blockIdx.x;
    int tid = threadIdx.x;
    int c = tid & 63, nq = tid >> 6;
    float acc = 0.f;
    for (int n = nq; n < NT; n += 4) acc += x[((size_t)b * NT + n) * 64 + c];
    __shared__ float sm[256];
    sm[tid] = acc;
    __syncthreads();
    if (tid < 64) g[b * 64 + tid] = sm[tid] + sm[64 + tid] + sm[128 + tid] + sm[192 + tid];
}

__global__ void z2_kernel(const float* __restrict__ g, const float* __restrict__ wg,
                          const float* __restrict__ bg, const float* __restrict__ wv,
                          float* __restrict__ z2) {
    int b = blockIdx.x;
    int c = threadIdx.x;
    float acc = bg[c];
    for (int k = 0; k < 64; k++) acc += g[b * 64 + k] * wg[c * 64 + k];
    float y = fmaxf(acc, 0.f) * wv[64 + c];
    __shared__ float sm[64];
    sm[c] = y;
    __syncthreads();
    if (c == 0) {
        float t = 0.f;
        for (int k = 0; k < 64; k++) t += sm[k];
        z2[b] = t;
    }
}

__global__ __launch_bounds__(256) void final_kernel(
    const float* __restrict__ x,
    const float* __restrict__ wn, const float* __restrict__ bn,
    const float* __restrict__ wv, const float* __restrict__ bv,
    const float* __restrict__ z2, float* __restrict__ out)
{
    __shared__ float wns[64][65];
    __shared__ float bns[64], wvs[64];
    int tid = threadIdx.x;
#pragma unroll
    for (int l = 0; l < 16; l++) {
        int f = tid + l * 256;
        wns[f >> 6][f & 63] = wn[f];
    }
    if (tid < 64) { bns[tid] = bn[tid]; wvs[tid] = wv[tid]; }
    __syncthreads();

    int row = blockIdx.x * 64 + (tid >> 2);
    int q = tid & 3;
    float xr[64];
#pragma unroll
    for (int k = 0; k < 64; k++) xr[k] = x[(size_t)row * 64 + k];
    float y = 0.f;
    for (int c16 = 0; c16 < 16; c16++) {
        int c = q * 16 + c16;
        float acc = bns[c];
#pragma unroll
        for (int k = 0; k < 64; k++) acc += xr[k] * wns[c][k];
        y += fmaxf(acc, 0.f) * wvs[c];
    }
    y += __shfl_xor_sync(0xffffffffu, y, 1);
    y += __shfl_xor_sync(0xffffffffu, y, 2);
    if (q == 0) out[row] = y + z2[row >> 10] + bv[0];
}

// ---------------- launch ----------------------------------------------------
extern "C" void kernel_launch(void* const* d_in, const int* in_sizes, int n_in,
                              void* d_out, int out_size)
{
    const float* xin = (const float*)d_in[0];
    const int*   adj = (const int*)d_in[1];
    const float* w1  = (const float*)d_in[2];
    const float* as1 = (const float*)d_in[3];
    const float* ad1 = (const float*)d_in[4];
    const float* b1  = (const float*)d_in[5];
    const float* w2  = (const float*)d_in[6];
    const float* as2 = (const float*)d_in[7];
    const float* ad2 = (const float*)d_in[8];
    const float* b2  = (const float*)d_in[9];
    const float* w3  = (const float*)d_in[10];
    const float* as3 = (const float*)d_in[11];
    const float* ad3 = (const float*)d_in[12];
    const float* b3  = (const float*)d_in[13];
    const float* wn  = (const float*)d_in[14];
    const float* bn  = (const float*)d_in[15];
    const float* wg  = (const float*)d_in[16];
    const float* bg  = (const float*)d_in[17];
    const float* wv  = (const float*)d_in[18];
    const float* bv  = (const float*)d_in[19];
    float* out = (float*)d_out;

    float *bufA, *bufB, *sA, *EsA, *Es2A, *gsm, *z2p;
    float4* dpk;
    __nv_bfloat16 *hhi, *hlo;
    u32* bits;
    cudaGetSymbolAddress((void**)&bufA, g_bufA);
    cudaGetSymbolAddress((void**)&bufB, g_bufB);
    cudaGetSymbolAddress((void**)&sA,   g_sj);
    cudaGetSymbolAddress((void**)&EsA,  g_Esj);
    cudaGetSymbolAddress((void**)&Es2A, g_Es2);
    cudaGetSymbolAddress((void**)&dpk,  g_dpk);
    cudaGetSymbolAddress((void**)&hhi,  g_hThi);
    cudaGetSymbolAddress((void**)&hlo,  g_hTlo);
    cudaGetSymbolAddress((void**)&bits, g_bits);
    cudaGetSymbolAddress((void**)&gsm,  g_gsum);
    cudaGetSymbolAddress((void**)&z2p,  g_z2);

    const int M = BATCH * NT;
    const ull* bits64 = (const ull*)bits;

    pack_adj_kernel<<<M, 32>>>(adj, bits);

    // layer 1: 64 -> 4x64
    gemm_xwT<<<dim3(M / 128, 4), 256>>>(xin, w1, bufA, M, 64, 256);
    scores_kernel<<<(M * 32) / 256, 256>>>(bufA, as1, ad1, sA, EsA, Es2A, dpk, 4);
    transpose_kernel<<<dim3(16, 4, BATCH), 256>>>(bufA, hhi, hlo, 4);
    agg_mma_kernel<<<dim3(NT / 128, 4, BATCH), 256>>>(
        hhi, hlo, sA, EsA, Es2A, dpk, bits64, b1, bufB, 4);

    // layer 2: 4x64 -> 4x64
    gemm_xwT<<<dim3(M / 128, 4), 256>>>(bufB, w2, bufA, M, 256, 256);
    scores_kernel<<<(M * 32) / 256, 256>>>(bufA, as2, ad2, sA, EsA, Es2A, dpk, 4);
    transpose_kernel<<<dim3(16, 4, BATCH), 256>>>(bufA, hhi, hlo, 4);
    agg_mma_kernel<<<dim3(NT / 128, 4, BATCH), 256>>>(
        hhi, hlo, sA, EsA, Es2A, dpk, bits64, b2, bufB, 4);

    // layer 3: 4x64 -> 64 (H=1)
    gemm_xwT<<<dim3(M / 128, 1), 256>>>(bufB, w3, bufA, M, 256, 64);
    scores_kernel<<<(M * 32) / 256, 256>>>(bufA, as3, ad3, sA, EsA, Es2A, dpk, 1);
    transpose_kernel<<<dim3(16, 1, BATCH), 256>>>(bufA, hhi, hlo, 1);
    agg_mma_kernel<<<dim3(NT / 128, 1, BATCH), 256>>>(
        hhi, hlo, sA, EsA, Es2A, dpk, bits64, b3, bufB, 1);

    // readout
    gsum_kernel<<<BATCH, 256>>>(bufB, gsm);
    z2_kernel<<<BATCH, 64>>>(gsm, wg, bg, wv, z2p);
    final_kernel<<<M / 64, 256>>>(bufB, wn, bn, wv, bv, z2p, out);
}